// round 4
// baseline (speedup 1.0000x reference)
#include <cuda_runtime.h>
#include <cstddef>
#include <cstdint>

// ---------------------------------------------------------------------------
// Problem constants
// ---------------------------------------------------------------------------
#define MAXN  100000
#define MAXE  200000
#define MAXC5 30000
#define MAXC6 30000
#define MAXC  (MAXC5 + MAXC6)
#define MAXR  (5*MAXC5 + 6*MAXC6)   // 330000
#define NCAP  64                    // node bucket capacity (Poisson lambda=4)
#define ECAP  64                    // edge bucket capacity (Poisson lambda=3.3)

// ---------------------------------------------------------------------------
// Scratch (device globals; no allocation anywhere)
// ---------------------------------------------------------------------------
__device__ float g_edge_h[MAXE*128];
__device__ float g_S     [MAXC*128];
__device__ float g_lvl_ne[MAXN*128];
__device__ float g_lvl   [MAXR*128];
__device__ float g_lvl_ec[MAXE*128];
__device__ float g_inter [MAXE*256];
__device__ float g_eo1   [MAXE*128];
__device__ float g_eo2   [MAXE*128];
__device__ int   g_ei [MAXR];
__device__ int   g_ep [MAXR];
__device__ int   g_cid[MAXR];
__device__ int   g_ncnt[MAXN];
__device__ int   g_ecnt[MAXE];
__device__ int   g_ntab[(size_t)MAXN*NCAP];
__device__ int   g_etab[(size_t)MAXE*ECAP];
// transposed weights Wt[n][k] (K contiguous)
__device__ float g_Wt[245760];
#define WT_NE_L1   0
#define WT_NE_L2   32768
#define WT_NE_LIFT 49152
#define WT_EC_L1   65536
#define WT_EC_L2   131072
#define WT_EC_LIFT 147456
#define WT_MLP     212992

// ---------------------------------------------------------------------------
// Helpers
// ---------------------------------------------------------------------------
__device__ __forceinline__ float to_tf32(float x){
  float y; asm("cvt.rna.tf32.f32 %0, %1;" : "=f"(y) : "f"(x)); return y;
}
__device__ __forceinline__ float4 ld4(const float* p){ return *reinterpret_cast<const float4*>(p); }
__device__ __forceinline__ float4 add4(float4 a, float4 b){ return make_float4(a.x+b.x, a.y+b.y, a.z+b.z, a.w+b.w); }
__device__ __forceinline__ float4 axpy4(float c, float4 a, float4 b){
  return make_float4(fmaf(c,a.x,b.x), fmaf(c,a.y,b.y), fmaf(c,a.z,b.z), fmaf(c,a.w,b.w));
}
__device__ __forceinline__ float4 scal4(float c, float4 a){ return make_float4(c*a.x, c*a.y, c*a.z, c*a.w); }
__device__ __forceinline__ float4 tf4(float4 a){
  return make_float4(to_tf32(a.x), to_tf32(a.y), to_tf32(a.z), to_tf32(a.w));
}
__device__ __forceinline__ void mma_tf32(float* c, const uint32_t* a, const uint32_t* b){
  asm volatile(
    "mma.sync.aligned.m16n8k8.row.col.f32.tf32.tf32.f32 "
    "{%0,%1,%2,%3}, {%4,%5,%6,%7}, {%8,%9}, {%0,%1,%2,%3};"
    : "+f"(c[0]), "+f"(c[1]), "+f"(c[2]), "+f"(c[3])
    : "r"(a[0]), "r"(a[1]), "r"(a[2]), "r"(a[3]), "r"(b[0]), "r"(b[1]));
}

// ---------------------------------------------------------------------------
// Aux kernels
// ---------------------------------------------------------------------------
// Per-row metadata + edge-CSR fill (row r pushed into buckets ei[r] and ep[r])
__global__ void meta_k(const int* __restrict__ c5, const int* __restrict__ c6,
                       int C5, int C6, int R,
                       int* ei, int* ep, int* cid,
                       int* ecnt, int* etab)
{
  int r = blockIdx.x*blockDim.x + threadIdx.x;
  if (r >= R) return;
  int e, p, c;
  int base5 = 5*C5;
  if (r < base5){
    c = r/5; int i = r - c*5;
    e = c5[c*5 + i];
    p = c5[c*5 + (i+4)%5];
  } else {
    int rr = r - base5;
    c = rr/6; int i = rr - c*6;
    e = c6[c*6 + i];
    p = c6[c*6 + (i+5)%6];
    c += C5;
  }
  ei[r] = e; ep[r] = p; cid[r] = c;
  int t0 = atomicAdd(&ecnt[e], 1);
  if (t0 < ECAP) etab[(size_t)e*ECAP + t0] = r;
  int t1 = atomicAdd(&ecnt[p], 1);
  if (t1 < ECAP) etab[(size_t)p*ECAP + t1] = r;
}

// node-CSR fill: edge e pushed into buckets u and v
__global__ void nodecsr_k(const int* __restrict__ en, int E, int* ncnt, int* ntab)
{
  int e = blockIdx.x*blockDim.x + threadIdx.x;
  if (e >= E) return;
  int u = en[2*e], v = en[2*e+1];
  int t0 = atomicAdd(&ncnt[u], 1);
  if (t0 < NCAP) ntab[(size_t)u*NCAP + t0] = e;
  int t1 = atomicAdd(&ncnt[v], 1);
  if (t1 < NCAP) ntab[(size_t)v*NCAP + t1] = e;
}

// Per-cycle edge sum: S[c] = 2 * sum_i edge_rep[edges(c,i)]
__global__ void sum_k(const float* __restrict__ edge,
                      const int* __restrict__ c5, const int* __restrict__ c6,
                      int C5, float* __restrict__ S)
{
  int c = blockIdx.x, t = threadIdx.x;
  float s = 0.f;
  if (c < C5){
    const int* e = c5 + (size_t)c*5;
    #pragma unroll
    for (int i=0;i<5;i++) s += edge[(size_t)e[i]*128 + t];
  } else {
    const int* e = c6 + (size_t)(c - C5)*6;
    #pragma unroll
    for (int i=0;i<6;i++) s += edge[(size_t)e[i]*128 + t];
  }
  S[(size_t)c*128 + t] = 2.0f*s;
}

// lvl_ne[n] = sum over incident edges of edge_h  (gather, no atomics)
__global__ void nodegather_k(const float* __restrict__ edge_h,
                             const int* __restrict__ ncnt, const int* __restrict__ ntab,
                             float* __restrict__ lvl_ne)
{
  int n = blockIdx.x, t = threadIdx.x;
  __shared__ int idx[NCAP];
  int d = min(ncnt[n], NCAP);
  if (t < d) idx[t] = ntab[(size_t)n*NCAP + t];
  __syncthreads();
  float s = 0.f;
  for (int i = 0; i < d; i++)
    s += edge_h[(size_t)idx[i]*128 + t];
  lvl_ne[(size_t)n*128 + t] = s;
}

// lvl_ec[e] = sum lvl[r]; inter[e] = sum cyc[r]  over CSR bucket of e
__global__ void edgegather_k(const float* __restrict__ lvl, const float* __restrict__ cyc,
                             const int* __restrict__ ecnt, const int* __restrict__ etab,
                             float* __restrict__ lvl_ec, float* __restrict__ inter)
{
  int e = blockIdx.x, t = threadIdx.x;
  __shared__ int idx[ECAP];
  int d = min(ecnt[e], ECAP);
  if (t < d) idx[t] = etab[(size_t)e*ECAP + t];
  __syncthreads();
  float s = 0.f, w0 = 0.f, w1 = 0.f;
  for (int i = 0; i < d; i++){
    int r = idx[i];
    s  += lvl[(size_t)r*128 + t];
    w0 += cyc[(size_t)r*256 + t];
    w1 += cyc[(size_t)r*256 + 128 + t];
  }
  lvl_ec[(size_t)e*128 + t] = s;
  inter [(size_t)e*256 + t]       = w0;
  inter [(size_t)e*256 + 128 + t] = w1;
}

// 32x32 tiled transpose: out[n*K+k] = in[k*N+n]
__global__ void transpose_k(const float* __restrict__ in, float* __restrict__ out,
                            int K, int N)
{
  __shared__ float t[32][33];
  int kb = blockIdx.y*32, nb = blockIdx.x*32;
  #pragma unroll
  for (int i=0;i<4;i++){
    int k = kb + threadIdx.y + i*8;
    t[threadIdx.y + i*8][threadIdx.x] = in[(size_t)k*N + nb + threadIdx.x];
  }
  __syncthreads();
  #pragma unroll
  for (int i=0;i<4;i++){
    int n = nb + threadIdx.y + i*8;
    out[(size_t)n*K + kb + threadIdx.x] = t[threadIdx.x][threadIdx.y + i*8];
  }
}

// ---------------------------------------------------------------------------
// Fused tensor-core GEMM (tf32 mma.sync), software-pipelined.
// Tile 128x128xK32; 256 thr = 8 warps; warp tile 32x64.
// ---------------------------------------------------------------------------
struct GemmArgs {
  const float* B;          // Wt base [Ntotal][K] (K contiguous)
  float*       out;
  const float* a0; const float* a1; const float* a2;
  const int*   idx0; const int* idx1; const int* idx2;
  const float* sp0; const float* sp1;
  int M, K, ldo;
};

// Modes (A row construction, 8 floats at (r, k..k+8)):
// 1: [node[u]+node[v] | edge]            K=256
// 2: c0*node + lvl_ne                    K=128
// 3: c0*edge_h + node[u]+node[v]         K=128
// 4: [edge[ei]+edge[ep] | S[c] | cyc[r]] K=512
// 5: c0*edge + c1*lvl_ec                 K=128
// 6: c0*(int[ei]+int[ep]) + [edge[ei]+edge[ep] | S[c]]  K=256
// 7: [eo1 | eo2]                         K=256
template<int MODE>
__device__ __forceinline__ void loadA(const GemmArgs& g, int r, int k, bool valid,
                                      float c0, float c1, float4& o0, float4& o1)
{
  if (!valid){ o0 = make_float4(0,0,0,0); o1 = o0; return; }
  if constexpr (MODE == 1){
    if (k < 128){
      int u = g.idx0[2*r], v = g.idx0[2*r+1];
      const float* pu = g.a0 + (size_t)u*128 + k;
      const float* pv = g.a0 + (size_t)v*128 + k;
      o0 = add4(ld4(pu), ld4(pv)); o1 = add4(ld4(pu+4), ld4(pv+4));
    } else {
      const float* p = g.a1 + (size_t)r*128 + (k-128);
      o0 = ld4(p); o1 = ld4(p+4);
    }
  } else if constexpr (MODE == 2){
    const float* p0 = g.a0 + (size_t)r*128 + k;
    const float* p1 = g.a1 + (size_t)r*128 + k;
    o0 = axpy4(c0, ld4(p0), ld4(p1)); o1 = axpy4(c0, ld4(p0+4), ld4(p1+4));
  } else if constexpr (MODE == 3){
    int u = g.idx0[2*r], v = g.idx0[2*r+1];
    const float* ph = g.a0 + (size_t)r*128 + k;
    const float* pu = g.a1 + (size_t)u*128 + k;
    const float* pv = g.a1 + (size_t)v*128 + k;
    o0 = axpy4(c0, ld4(ph),   add4(ld4(pu),   ld4(pv)));
    o1 = axpy4(c0, ld4(ph+4), add4(ld4(pu+4), ld4(pv+4)));
  } else if constexpr (MODE == 4){
    if (k < 128){
      int ei = g.idx0[r], ep = g.idx1[r];
      const float* p0 = g.a0 + (size_t)ei*128 + k;
      const float* p1 = g.a0 + (size_t)ep*128 + k;
      o0 = add4(ld4(p0), ld4(p1)); o1 = add4(ld4(p0+4), ld4(p1+4));
    } else if (k < 256){
      int c = g.idx2[r];
      const float* p = g.a1 + (size_t)c*128 + (k-128);
      o0 = ld4(p); o1 = ld4(p+4);
    } else {
      const float* p = g.a2 + (size_t)r*256 + (k-256);
      o0 = ld4(p); o1 = ld4(p+4);
    }
  } else if constexpr (MODE == 5){
    const float* p0 = g.a0 + (size_t)r*128 + k;
    const float* p1 = g.a1 + (size_t)r*128 + k;
    o0 = add4(scal4(c0, ld4(p0)),   scal4(c1, ld4(p1)));
    o1 = add4(scal4(c0, ld4(p0+4)), scal4(c1, ld4(p1+4)));
  } else if constexpr (MODE == 6){
    int ei = g.idx0[r], ep = g.idx1[r];
    const float* p0 = g.a0 + (size_t)ei*256 + k;
    const float* p1 = g.a0 + (size_t)ep*256 + k;
    float4 b0 = add4(ld4(p0),   ld4(p1));
    float4 b1 = add4(ld4(p0+4), ld4(p1+4));
    float4 l0, l1;
    if (k < 128){
      const float* q0 = g.a1 + (size_t)ei*128 + k;
      const float* q1 = g.a1 + (size_t)ep*128 + k;
      l0 = add4(ld4(q0), ld4(q1)); l1 = add4(ld4(q0+4), ld4(q1+4));
    } else {
      int c = g.idx2[r];
      const float* q = g.a2 + (size_t)c*128 + (k-128);
      l0 = ld4(q); l1 = ld4(q+4);
    }
    o0 = axpy4(c0, b0, l0); o1 = axpy4(c0, b1, l1);
  } else { // MODE 7
    const float* p = (k < 128) ? (g.a0 + (size_t)r*128 + k)
                               : (g.a1 + (size_t)r*128 + (k-128));
    o0 = ld4(p); o1 = ld4(p+4);
  }
}

#define ASTRIDE 36   // padded row stride (floats) — conflict-free fragment loads

template<int MODE>
__global__ void __launch_bounds__(256, 2) mgemm_k(GemmArgs g)
{
  __shared__ float As[128][ASTRIDE];
  __shared__ float Bs[128][ASTRIDE];

  const int tid  = threadIdx.x;
  const int lane = tid & 31;
  const int wid  = tid >> 5;
  const int gq   = lane >> 2;     // group 0..7
  const int tig  = lane & 3;      // thread-in-group
  const int warp_m = wid >> 1, warp_n = wid & 1;
  const int m_base = warp_m * 32, n_base = warp_n * 64;
  const int row0 = blockIdx.y * 128;
  const int col0 = blockIdx.x * 128;

  // Loader mapping: 2 threads per row, 16 floats each
  const int ar   = tid >> 1;
  const int half = tid & 1;
  const int r    = row0 + ar;
  const bool vrow = (r < g.M);

  const float c0 = g.sp0 ? (1.0f + *g.sp0) : 1.0f;
  const float c1 = g.sp1 ? (1.0f + *g.sp1) : 1.0f;

  const float* bptr = g.B + (size_t)(col0 + ar) * g.K + half*16;

  float acc[2][8][4];
  #pragma unroll
  for (int mi=0;mi<2;mi++)
    #pragma unroll
    for (int ni=0;ni<8;ni++)
      #pragma unroll
      for (int i=0;i<4;i++) acc[mi][ni][i] = 0.f;

  // prefetch chunk 0
  float4 pa0, pa1, pa2, pa3, pb0, pb1, pb2, pb3;
  loadA<MODE>(g, r, half*16,     vrow, c0, c1, pa0, pa1);
  loadA<MODE>(g, r, half*16 + 8, vrow, c0, c1, pa2, pa3);
  pb0 = ld4(bptr); pb1 = ld4(bptr + 4); pb2 = ld4(bptr + 8); pb3 = ld4(bptr + 12);

  const int nK = g.K >> 5;
  for (int kt = 0; kt < nK; kt++){
    // store prefetched chunk to smem (tf32-rounded)
    {
      float* pa = &As[ar][half*16];
      *reinterpret_cast<float4*>(pa)      = tf4(pa0);
      *reinterpret_cast<float4*>(pa + 4)  = tf4(pa1);
      *reinterpret_cast<float4*>(pa + 8)  = tf4(pa2);
      *reinterpret_cast<float4*>(pa + 12) = tf4(pa3);
      float* pb = &Bs[ar][half*16];
      *reinterpret_cast<float4*>(pb)      = tf4(pb0);
      *reinterpret_cast<float4*>(pb + 4)  = tf4(pb1);
      *reinterpret_cast<float4*>(pb + 8)  = tf4(pb2);
      *reinterpret_cast<float4*>(pb + 12) = tf4(pb3);
    }
    __syncthreads();

    // issue next chunk's loads (overlap with mma below)
    if (kt + 1 < nK){
      const int k0 = (kt + 1) * 32;
      loadA<MODE>(g, r, k0 + half*16,     vrow, c0, c1, pa0, pa1);
      loadA<MODE>(g, r, k0 + half*16 + 8, vrow, c0, c1, pa2, pa3);
      pb0 = ld4(bptr + k0);     pb1 = ld4(bptr + k0 + 4);
      pb2 = ld4(bptr + k0 + 8); pb3 = ld4(bptr + k0 + 12);
    }

    #pragma unroll
    for (int ks = 0; ks < 4; ks++){
      const int kk = ks * 8;
      uint32_t af[2][4];
      #pragma unroll
      for (int mi = 0; mi < 2; mi++){
        const int mrow = m_base + mi*16 + gq;
        af[mi][0] = __float_as_uint(As[mrow    ][kk + tig]);
        af[mi][1] = __float_as_uint(As[mrow + 8][kk + tig]);
        af[mi][2] = __float_as_uint(As[mrow    ][kk + tig + 4]);
        af[mi][3] = __float_as_uint(As[mrow + 8][kk + tig + 4]);
      }
      uint32_t bf[8][2];
      #pragma unroll
      for (int ni = 0; ni < 8; ni++){
        const int nrow = n_base + ni*8 + gq;
        bf[ni][0] = __float_as_uint(Bs[nrow][kk + tig]);
        bf[ni][1] = __float_as_uint(Bs[nrow][kk + tig + 4]);
      }
      #pragma unroll
      for (int mi = 0; mi < 2; mi++)
        #pragma unroll
        for (int ni = 0; ni < 8; ni++)
          mma_tf32(acc[mi][ni], af[mi], bf[ni]);
    }
    __syncthreads();
  }

  // Epilogue: relu + store. c-frag rows gq / gq+8, cols 2*tig / 2*tig+1.
  #pragma unroll
  for (int mi = 0; mi < 2; mi++){
    #pragma unroll
    for (int rsel = 0; rsel < 2; rsel++){
      const int rr = row0 + m_base + mi*16 + gq + rsel*8;
      if (rr < g.M){
        #pragma unroll
        for (int ni = 0; ni < 8; ni++){
          const int cc = col0 + n_base + ni*8 + 2*tig;
          float v0 = fmaxf(acc[mi][ni][rsel*2],     0.0f);
          float v1 = fmaxf(acc[mi][ni][rsel*2 + 1], 0.0f);
          *reinterpret_cast<float2*>(g.out + (size_t)rr * g.ldo + cc) = make_float2(v0, v1);
        }
      }
    }
  }
}

// ---------------------------------------------------------------------------
// Launcher
// ---------------------------------------------------------------------------
extern "C" void kernel_launch(void* const* d_in, const int* in_sizes, int n_in,
                              void* d_out, int out_size)
{
  const float* node      = (const float*)d_in[0];
  const float* edge      = (const float*)d_in[1];
  const float* cyc       = (const float*)d_in[2];
  const float* ne_lift_W = (const float*)d_in[3];
  const float* ne_l1_W   = (const float*)d_in[4];
  const float* ne_l2_W   = (const float*)d_in[5];
  const float* ec_lift_W = (const float*)d_in[6];
  const float* ec_l1_W   = (const float*)d_in[7];
  const float* ec_l2_W   = (const float*)d_in[8];
  const float* mlp_W     = (const float*)d_in[9];
  const float* eps1      = (const float*)d_in[10];
  const float* eps2      = (const float*)d_in[11];
  const float* e11       = (const float*)d_in[12];
  const float* e12       = (const float*)d_in[13];
  const float* e2        = (const float*)d_in[14];
  const int*   edge_nodes= (const int*)  d_in[15];
  const int*   c5        = (const int*)  d_in[16];
  const int*   c6        = (const int*)  d_in[17];

  const int N  = in_sizes[0]  / 128;
  const int E  = in_sizes[1]  / 128;
  const int C5 = in_sizes[16] / 5;
  const int C6 = in_sizes[17] / 6;
  const int R  = 5*C5 + 6*C6;
  float* out = (float*)d_out;

  float *edge_h, *S, *lvl_ne, *lvl, *lvl_ec, *inter, *eo1, *eo2, *Wt;
  int *ei, *ep, *cid, *ncnt, *ecnt, *ntab, *etab;
  cudaGetSymbolAddress((void**)&edge_h, g_edge_h);
  cudaGetSymbolAddress((void**)&S,      g_S);
  cudaGetSymbolAddress((void**)&lvl_ne, g_lvl_ne);
  cudaGetSymbolAddress((void**)&lvl,    g_lvl);
  cudaGetSymbolAddress((void**)&lvl_ec, g_lvl_ec);
  cudaGetSymbolAddress((void**)&inter,  g_inter);
  cudaGetSymbolAddress((void**)&eo1,    g_eo1);
  cudaGetSymbolAddress((void**)&eo2,    g_eo2);
  cudaGetSymbolAddress((void**)&Wt,     g_Wt);
  cudaGetSymbolAddress((void**)&ei,   g_ei);
  cudaGetSymbolAddress((void**)&ep,   g_ep);
  cudaGetSymbolAddress((void**)&cid,  g_cid);
  cudaGetSymbolAddress((void**)&ncnt, g_ncnt);
  cudaGetSymbolAddress((void**)&ecnt, g_ecnt);
  cudaGetSymbolAddress((void**)&ntab, g_ntab);
  cudaGetSymbolAddress((void**)&etab, g_etab);

  cudaMemsetAsync(ncnt, 0, (size_t)N*sizeof(int), 0);
  cudaMemsetAsync(ecnt, 0, (size_t)E*sizeof(int), 0);

  // transpose weights -> Wt[n][k]
  dim3 tb(32, 8);
  transpose_k<<<dim3(4,  8), tb>>>(ne_l1_W,   Wt + WT_NE_L1,   256, 128);
  transpose_k<<<dim3(4,  4), tb>>>(ne_l2_W,   Wt + WT_NE_L2,   128, 128);
  transpose_k<<<dim3(4,  4), tb>>>(ne_lift_W, Wt + WT_NE_LIFT, 128, 128);
  transpose_k<<<dim3(4, 16), tb>>>(ec_l1_W,   Wt + WT_EC_L1,   512, 128);
  transpose_k<<<dim3(4,  4), tb>>>(ec_l2_W,   Wt + WT_EC_L2,   128, 128);
  transpose_k<<<dim3(8,  8), tb>>>(ec_lift_W, Wt + WT_EC_LIFT, 256, 256);
  transpose_k<<<dim3(4,  8), tb>>>(mlp_W,     Wt + WT_MLP,     256, 128);

  meta_k<<<(R + 255)/256, 256>>>(c5, c6, C5, C6, R, ei, ep, cid, ecnt, etab);
  nodecsr_k<<<(E + 255)/256, 256>>>(edge_nodes, E, ncnt, ntab);
  sum_k<<<C5 + C6, 128>>>(edge, c5, c6, C5, S);

  // G1: edge_h = relu([node[u]+node[v] | edge] @ ne_l1_W)
  {
    GemmArgs a{}; a.B = Wt + WT_NE_L1; a.M = E; a.K = 256;
    a.out = edge_h; a.ldo = 128;
    a.a0 = node; a.a1 = edge; a.idx0 = edge_nodes;
    mgemm_k<1><<<dim3(1, (E + 127)/128), 256>>>(a);
  }
  // lvl_ne = node-gather of edge_h
  nodegather_k<<<N, 128>>>(edge_h, ncnt, ntab, lvl_ne);

  // G2: node_out = relu(((1+eps1)*node + lvl_ne) @ ne_l2_W)
  {
    GemmArgs a{}; a.B = Wt + WT_NE_L2; a.M = N; a.K = 128;
    a.out = out; a.ldo = 128;
    a.a0 = node; a.a1 = lvl_ne; a.sp0 = eps1;
    mgemm_k<2><<<dim3(1, (N + 127)/128), 256>>>(a);
  }
  // G3: edge_out_1 = relu(((1+eps2)*edge_h + node[u]+node[v]) @ ne_lift_W)
  {
    GemmArgs a{}; a.B = Wt + WT_NE_LIFT; a.M = E; a.K = 128;
    a.out = eo1; a.ldo = 128;
    a.a0 = edge_h; a.a1 = node; a.idx0 = edge_nodes; a.sp0 = eps2;
    mgemm_k<3><<<dim3(1, (E + 127)/128), 256>>>(a);
  }
  // G4: lvl = relu([e2c | S | cyc_rep] @ ec_l1_W)
  {
    GemmArgs a{}; a.B = Wt + WT_EC_L1; a.M = R; a.K = 512;
    a.out = lvl; a.ldo = 128;
    a.a0 = edge; a.a1 = S; a.a2 = cyc;
    a.idx0 = ei; a.idx1 = ep; a.idx2 = cid;
    mgemm_k<4><<<dim3(1, (R + 127)/128), 256>>>(a);
  }
  // lvl_ec / inter = edge-gather of lvl / cyc
  edgegather_k<<<E, 128>>>(lvl, cyc, ecnt, etab, lvl_ec, inter);

  // G5: edge_out_2 = relu(((1+e11)*edge + (1+e12)*lvl_ec) @ ec_l2_W)
  {
    GemmArgs a{}; a.B = Wt + WT_EC_L2; a.M = E; a.K = 128;
    a.out = eo2; a.ldo = 128;
    a.a0 = edge; a.a1 = lvl_ec; a.sp0 = e11; a.sp1 = e12;
    mgemm_k<5><<<dim3(1, (E + 127)/128), 256>>>(a);
  }
  // G6: cycle_out = relu(((1+e2)*lin + lift) @ ec_lift_W)  (N=256 -> grid.x=2)
  {
    GemmArgs a{}; a.B = Wt + WT_EC_LIFT; a.M = R; a.K = 256;
    a.out = out + (size_t)(N + E)*128; a.ldo = 256;
    a.a0 = inter; a.a1 = edge; a.a2 = S;
    a.idx0 = ei; a.idx1 = ep; a.idx2 = cid; a.sp0 = e2;
    mgemm_k<6><<<dim3(2, (R + 127)/128), 256>>>(a);
  }
  // G7: edge_out = relu([eo1 | eo2] @ mlp_W)
  {
    GemmArgs a{}; a.B = Wt + WT_MLP; a.M = E; a.K = 256;
    a.out = out + (size_t)N*128; a.ldo = 128;
    a.a0 = eo1; a.a1 = eo2;
    mgemm_k<7><<<dim3(1, (E + 127)/128), 256>>>(a);
  }
}